// round 14
// baseline (speedup 1.0000x reference)
#include <cuda_runtime.h>
#include <cuda_bf16.h>

#define NL    64
#define HH    50
#define G4    200
#define DIN   60
#define BATCH 32
#define TT    2048
#define DOUT  50
#define BS    16
#define NSL   2
#define RINGN 16
#define TPB   448   // 14 warps; warps 0..12 do MMA

#define KSTEPS 21   // 336 folded K
// ---- scratch (device globals) ----
__device__ float d_ring[(NL - 1) * RINGN * NSL * HH * BS];  // [l][slot][s][u][16]
__device__ int   d_prog[NSL * NL];
__device__ int   d_cons[NSL * NL];
__device__ float d_xT[TT * NSL * DIN * BS];                 // [t][s][d][16]
__device__ float d_hT[TT * NSL * HH * BS];                  // [t][s][u][16]

// lstm smem (float indices)
#define OFF_BIAS 0       // [208]
#define OFF_G    208     // [208][20] gates fp32
#define OFF_ZP   4368    // zpack: 168 kpairs x 24 words (pair-packed bf16)
#define SMEM_FLOATS 8400
// fc smem
#define FOFF_W  0
#define FOFF_B  2512
#define FOFF_H  2576

__device__ __forceinline__ float sigf(float x) {
    return __fdividef(1.0f, 1.0f + __expf(-x));
}
__device__ __forceinline__ float tanhfast(float x) {
    return 1.0f - __fdividef(2.0f, __expf(2.0f * x) + 1.0f);
}
__device__ __forceinline__ int ld_acquire_gpu(const int* p) {
    int v;
    asm volatile("ld.acquire.gpu.global.b32 %0, [%1];" : "=r"(v) : "l"(p) : "memory");
    return v;
}
__device__ __forceinline__ void st_release_gpu(int* p, int v) {
    asm volatile("st.release.gpu.global.b32 [%0], %1;" :: "l"(p), "r"(v) : "memory");
}
__device__ __forceinline__ void mma_bf16(float* d, const unsigned int* a,
                                         unsigned int b0, unsigned int b1) {
    asm volatile(
        "mma.sync.aligned.m16n8k16.row.col.f32.bf16.bf16.f32 "
        "{%0,%1,%2,%3}, {%4,%5,%6,%7}, {%8,%9}, {%0,%1,%2,%3};"
        : "+f"(d[0]), "+f"(d[1]), "+f"(d[2]), "+f"(d[3])
        : "r"(a[0]), "r"(a[1]), "r"(a[2]), "r"(a[3]), "r"(b0), "r"(b1));
}

// stage one z value into the 3 folded-K bf16 slots (pair-packed words, row stride 24)
__device__ __forceinline__ void stage_z(__nv_bfloat16* zh, int n, int kk, float v) {
    __nv_bfloat16 z1 = __float2bfloat16(v);
    __nv_bfloat16 z2 = __float2bfloat16(v - __bfloat162float(z1));
    int k2 = 110 + kk, k3 = 220 + kk;
    zh[((kk >> 1) * 24 + n) * 2 + (kk & 1)] = z1;
    zh[((k2 >> 1) * 24 + n) * 2 + (k2 & 1)] = z2;
    zh[((k3 >> 1) * 24 + n) * 2 + (k3 & 1)] = z1;
}

__device__ __forceinline__ float wval(const float* wh, const float* wx,
                                      int j, int kz, int K1x) {
    if (kz < HH) return wh[j * HH + kz];
    int d = kz - HH;
    return (d < K1x) ? wx[j * K1x + d] : 0.0f;
}

__global__ void xpose_kernel(const float* __restrict__ x) {
    if (blockIdx.x == 0 && threadIdx.x < NSL * NL) {
        d_prog[threadIdx.x] = 0;
        d_cons[threadIdx.x] = 0;
    }
    int idx = blockIdx.x * blockDim.x + threadIdx.x;  // (b*DIN+d)*T + t
    if (idx >= BATCH * DIN * TT) return;
    int t = idx % TT;
    int bd = idx / TT;
    int d = bd % DIN, b = bd / DIN;
    d_xT[(((size_t)t * NSL + b / BS) * DIN + d) * BS + (b % BS)] = x[idx];
}

__global__ void __launch_bounds__(TPB, 1) lstm_kernel(
    const float* __restrict__ hn,  const float* __restrict__ cn,
    const float* __restrict__ Wih0, const float* __restrict__ Wih,
    const float* __restrict__ Whh, const float* __restrict__ bih,
    const float* __restrict__ bhh, const float* __restrict__ fcw,
    const float* __restrict__ fcb, float* __restrict__ out, int has_state)
{
    extern __shared__ float sm[];
    const int tid  = threadIdx.x;
    const int lane = tid & 31;
    const int w    = tid >> 5;

    // ================= FC consumer role (blocks 128,129) =================
    if (blockIdx.x >= NL * NSL) {
        const int s = blockIdx.x - NL * NSL;
        float* sm_w  = sm + FOFF_W;
        float* sm_fb = sm + FOFF_B;
        float* sm_h  = sm + FOFF_H;
        for (int i = tid; i < DOUT * HH; i += TPB) sm_w[i] = fcw[i];
        for (int i = tid; i < DOUT; i += TPB)      sm_fb[i] = fcb[i];
        __syncthreads();
        const int* prog63 = &d_prog[s * NL + NL - 1];
        for (int t = 0; t < TT; ++t) {
            if (lane == 0) { while (ld_acquire_gpu(prog63) < t + 1) __nanosleep(128); }
            __syncwarp();
            const float* hp = d_hT + ((size_t)t * NSL + s) * HH * BS;
            for (int idx = tid; idx < HH * 4; idx += TPB) {
                float4 v = __ldcg((const float4*)(hp + idx * 4));
                *(float4*)(sm_h + idx * 4) = v;
            }
            __syncthreads();
            if (tid < G4) {
                const int o  = tid % DOUT;
                const int bq = tid / DOUT;
#pragma unroll
                for (int i = 0; i < 4; ++i) {
                    int b = bq * 4 + i;
                    float acc = sm_fb[o];
#pragma unroll 5
                    for (int u = 0; u < HH; ++u)
                        acc = fmaf(sm_h[u * BS + b], sm_w[o * HH + u], acc);
                    out[((size_t)(s * BS + b) * DOUT + o) * TT + t] = sigf(acc);
                }
            }
            __syncthreads();
        }
        return;
    }

    // ========================= LSTM layer role =========================
    const int layer = blockIdx.x >> 1;
    const int s     = blockIdx.x & 1;
    const int b0    = s * BS;
    const int K1x   = (layer == 0) ? DIN : HH;

    float* sm_b = sm + OFF_BIAS;
    float* sm_g = sm + OFF_G;
    __nv_bfloat16* zh = reinterpret_cast<__nv_bfloat16*>(sm + OFF_ZP);

    // ---- init: zero zpack (NaN safety), bias ----
    for (int i = tid; i < 168 * 24; i += TPB) sm[OFF_ZP + i] = 0.0f;
    for (int jj = tid; jj < G4; jj += TPB)
        sm_b[jj] = bih[layer * G4 + jj] + bhh[layer * G4 + jj];

    // ---- A fragments into registers (once per layer) ----
    unsigned int afr[KSTEPS][4];
    {
        const float* wh = Whh + (size_t)layer * G4 * HH;
        const float* wx = (layer == 0) ? Wih0 : (Wih + (size_t)(layer - 1) * G4 * HH);
        const int gr = lane >> 2, cp = (lane & 3) * 2;
        if (w < 13) {
            for (int kk = 0; kk < KSTEPS; ++kk) {
#pragma unroll
                for (int r = 0; r < 4; ++r) {
                    int j = w * 16 + gr + (r & 1) * 8;
                    int c = kk * 16 + cp + (r >> 1) * 8;   // even; c,c+1 same segment
                    unsigned int pr = 0;
                    if (j < G4 && c < 330) {
                        int seg = c / 110;
#pragma unroll
                        for (int half = 0; half < 2; ++half) {
                            int kz = (c + half) % 110;
                            float wv = wval(wh, wx, j, kz, K1x);
                            __nv_bfloat16 w1 = __float2bfloat16(wv);
                            __nv_bfloat16 res = (seg < 2)
                                ? w1 : __float2bfloat16(wv - __bfloat162float(w1));
                            unsigned short bits = *reinterpret_cast<unsigned short*>(&res);
                            pr |= ((unsigned int)bits) << (half * 16);
                        }
                    }
                    afr[kk][r] = pr;
                }
            }
        } else {
            for (int kk = 0; kk < KSTEPS; ++kk)
#pragma unroll
                for (int r = 0; r < 4; ++r) afr[kk][r] = 0u;
        }
    }

    // ---- cell state in regs + h0 staging ----
    float creg[4];
    const int u_c  = tid % HH;
    const int bq_c = (tid < G4) ? (tid / HH) : 0;
    __syncthreads();   // zpack zeroed before staging
    if (tid < G4) {
#pragma unroll
        for (int i = 0; i < 4; ++i) {
            int b = 4 * bq_c + i;
            creg[i] = cn[((size_t)layer * BATCH + b0 + b) * HH + u_c];
            stage_z(zh, b, u_c, hn[((size_t)layer * BATCH + b0 + b) * HH + u_c]);
        }
    }
    __syncthreads();

    int* prog_prev = (layer > 0)      ? &d_prog[s * NL + layer - 1] : 0;
    int* cons_next = (layer < NL - 1) ? &d_cons[s * NL + layer + 1] : 0;
    int* prog_me   = &d_prog[s * NL + layer];
    int* cons_me   = &d_cons[s * NL + layer];

    // per-thread B-frag base (word offset inside a k-step block of 192 words)
    const int zb = (lane & 3) * 24 + (lane >> 2);
    const float* zpw = sm + OFF_ZP;

    for (int t = 0; t < TT; ++t) {
        // ---- Phase 1: poll prev, stage x(t) into z slots kk = 50..50+K1x ----
        if (layer > 0) {
            if (lane == 0) { while (ld_acquire_gpu(prog_prev) < t + 1) __nanosleep(32); }
            __syncwarp();
            const float* rp = d_ring +
                (((size_t)(layer - 1) * RINGN + (t & (RINGN - 1))) * NSL + s) * HH * BS;
            for (int idx = tid; idx < HH * BS; idx += TPB) {
                int d = idx >> 4, n = idx & 15;
                stage_z(zh, n, HH + d, __ldcg(rp + d * BS + n));
            }
        } else {
            const float* xp = d_xT + ((size_t)t * NSL + s) * DIN * BS;
            for (int idx = tid; idx < DIN * BS; idx += TPB) {
                int d = idx >> 4, n = idx & 15;
                stage_z(zh, n, HH + d, xp[d * BS + n]);
            }
        }
        __syncthreads();
        if (tid == 0 && layer > 0 && (((t & 3) == 3) || t == TT - 1))
            st_release_gpu(cons_me, t + 1);

        // ---- Phase 2: MMA warps compute gates ----
        if (w < 13) {
            float acc0[4] = {0.f, 0.f, 0.f, 0.f};
            float acc1[4] = {0.f, 0.f, 0.f, 0.f};
#pragma unroll
            for (int kk = 0; kk < KSTEPS; ++kk) {
                const float* zp = zpw + kk * 192 + zb;
                unsigned int b00 = __float_as_uint(zp[0]);
                unsigned int b01 = __float_as_uint(zp[96]);
                unsigned int b10 = __float_as_uint(zp[8]);
                unsigned int b11 = __float_as_uint(zp[104]);
                mma_bf16(acc0, afr[kk], b00, b01);
                mma_bf16(acc1, afr[kk], b10, b11);
            }
            const int gr = lane >> 2, cp = (lane & 3) * 2;
            const int j0 = w * 16 + gr;
            *(float2*)(sm_g + j0 * 20 + cp)           = make_float2(acc0[0], acc0[1]);
            *(float2*)(sm_g + (j0 + 8) * 20 + cp)     = make_float2(acc0[2], acc0[3]);
            *(float2*)(sm_g + j0 * 20 + cp + 8)       = make_float2(acc1[0], acc1[1]);
            *(float2*)(sm_g + (j0 + 8) * 20 + cp + 8) = make_float2(acc1[2], acc1[3]);
        }
        __syncthreads();

        // ---- ring backpressure (uniform per warp) ----
        if (layer < NL - 1 && t >= RINGN) {
            if (lane == 0) { while (ld_acquire_gpu(cons_next) < t - RINGN + 1) __nanosleep(32); }
            __syncwarp();
        }

        // ---- Phase 3: cell update (tid<200), stage h(t+1), publish ring ----
        if (tid < G4) {
            float4 gi4 = *(const float4*)(sm_g + u_c * 20 + 4 * bq_c);
            float4 gf4 = *(const float4*)(sm_g + (u_c + 50) * 20 + 4 * bq_c);
            float4 gg4 = *(const float4*)(sm_g + (u_c + 100) * 20 + 4 * bq_c);
            float4 go4 = *(const float4*)(sm_g + (u_c + 150) * 20 + 4 * bq_c);
            float bi = sm_b[u_c], bf = sm_b[u_c + 50], bg = sm_b[u_c + 100], bo = sm_b[u_c + 150];
            float gi[4] = {gi4.x + bi, gi4.y + bi, gi4.z + bi, gi4.w + bi};
            float gf[4] = {gf4.x + bf, gf4.y + bf, gf4.z + bf, gf4.w + bf};
            float gg[4] = {gg4.x + bg, gg4.y + bg, gg4.z + bg, gg4.w + bg};
            float go[4] = {go4.x + bo, go4.y + bo, go4.z + bo, go4.w + bo};
            float h4[4];
#pragma unroll
            for (int i = 0; i < 4; ++i) {
                float c = sigf(gf[i]) * creg[i] + sigf(gi[i]) * tanhfast(gg[i]);
                float h = sigf(go[i]) * tanhfast(c);
                creg[i] = c;
                h4[i] = h;
                stage_z(zh, 4 * bq_c + i, u_c, h);
            }
            float4 hv = make_float4(h4[0], h4[1], h4[2], h4[3]);
            float* dst = (layer < NL - 1)
                ? (d_ring + (((size_t)layer * RINGN + (t & (RINGN - 1))) * NSL + s) * HH * BS
                   + u_c * BS + 4 * bq_c)
                : (d_hT + ((size_t)t * NSL + s) * HH * BS + u_c * BS + 4 * bq_c);
            __stcg((float4*)dst, hv);
            if (t == TT - 1 && has_state) {
                size_t base2 = (size_t)BATCH * DOUT * TT;
#pragma unroll
                for (int i = 0; i < 4; ++i) {
                    size_t sidx = ((size_t)layer * BATCH + b0 + 4 * bq_c + i) * HH + u_c;
                    out[base2 + sidx] = h4[i];
                    out[base2 + (size_t)NL * BATCH * HH + sidx] = creg[i];
                }
            }
        }
        __syncthreads();
        if (tid == 0) st_release_gpu(prog_me, t + 1);
    }
}

extern "C" void kernel_launch(void* const* d_in, const int* in_sizes, int n_in,
                              void* d_out, int out_size) {
    const float* x    = (const float*)d_in[0];
    const float* hn   = (const float*)d_in[1];
    const float* cn   = (const float*)d_in[2];
    const float* Wih0 = (const float*)d_in[3];
    const float* Wih  = (const float*)d_in[4];
    const float* Whh  = (const float*)d_in[5];
    const float* bih  = (const float*)d_in[6];
    const float* bhh  = (const float*)d_in[7];
    const float* fcw  = (const float*)d_in[8];
    const float* fcb  = (const float*)d_in[9];
    float* out = (float*)d_out;

    const long long full = (long long)BATCH * DOUT * TT + 2LL * NL * BATCH * HH;
    int has_state = (out_size >= full) ? 1 : 0;

    cudaFuncSetAttribute(lstm_kernel, cudaFuncAttributeMaxDynamicSharedMemorySize,
                         SMEM_FLOATS * sizeof(float));

    xpose_kernel<<<(BATCH * DIN * TT + 255) / 256, 256>>>(x);
    lstm_kernel<<<NL * NSL + NSL, TPB, SMEM_FLOATS * sizeof(float)>>>(
        hn, cn, Wih0, Wih, Whh, bih, bhh, fcw, fcb, out, has_state);
}

// round 15
// speedup vs baseline: 1.4257x; 1.4257x over previous
#include <cuda_runtime.h>
#include <cuda_bf16.h>

#define NL    64
#define HH    50
#define G4    200
#define DIN   60
#define BATCH 32
#define TT    2048
#define DOUT  50
#define BS    16
#define NSL   2
#define RINGN 16
#define TPB   480   // warps 0-12: H/MMA group (tid 0..415), warps 13-14: X group (tid 416..479)

#define KST   22    // folded K: 10 h-ksteps + 12 x-ksteps
#define KH    10
// ---- scratch (device globals) ----
__device__ float d_ring[(NL - 1) * RINGN * NSL * HH * BS];  // [l][slot][s][u][16]
__device__ int   d_prog[NSL * NL];
__device__ int   d_cons[NSL * NL];
__device__ float d_xT[TT * NSL * DIN * BS];                 // [t][s][d][16]
__device__ float d_hT[TT * NSL * HH * BS];                  // [t][s][u][16]

// lstm smem (float indices)
#define OFF_BIAS 0       // [208]
#define OFF_G    208     // [208][20]
#define OFF_ZH   4368    // h-region zpack: 80 kpairs x 24 words = 1920
#define OFF_ZX   6288    // x-region zpack: 2 x (96 kpairs x 24 words = 2304)
#define SMEM_FLOATS 10896
// fc smem
#define FOFF_W  0
#define FOFF_B  2512
#define FOFF_H  2576

__device__ __forceinline__ float sigf(float x) {
    return __fdividef(1.0f, 1.0f + __expf(-x));
}
__device__ __forceinline__ float tanhfast(float x) {
    return 1.0f - __fdividef(2.0f, __expf(2.0f * x) + 1.0f);
}
__device__ __forceinline__ int ld_acquire_gpu(const int* p) {
    int v;
    asm volatile("ld.acquire.gpu.global.b32 %0, [%1];" : "=r"(v) : "l"(p) : "memory");
    return v;
}
__device__ __forceinline__ void st_release_gpu(int* p, int v) {
    asm volatile("st.release.gpu.global.b32 [%0], %1;" :: "l"(p), "r"(v) : "memory");
}
__device__ __forceinline__ void mma_bf16(float* d, const unsigned int* a,
                                         unsigned int b0, unsigned int b1) {
    asm volatile(
        "mma.sync.aligned.m16n8k16.row.col.f32.bf16.bf16.f32 "
        "{%0,%1,%2,%3}, {%4,%5,%6,%7}, {%8,%9}, {%0,%1,%2,%3};"
        : "+f"(d[0]), "+f"(d[1]), "+f"(d[2]), "+f"(d[3])
        : "r"(a[0]), "r"(a[1]), "r"(a[2]), "r"(a[3]), "r"(b0), "r"(b1));
}

#define BAR_SYNC(id, n)   asm volatile("bar.sync %0, %1;"   :: "r"(id), "r"(n) : "memory")
#define BAR_ARRIVE(id, n) asm volatile("bar.arrive %0, %1;" :: "r"(id), "r"(n) : "memory")

// pair-packed zpack write: word row stride 24, u16 idx = ((pos>>1)*24 + n)*2 + (pos&1)
__device__ __forceinline__ void zput(__nv_bfloat16* z, int n, int pos, __nv_bfloat16 v) {
    z[((pos >> 1) * 24 + n) * 2 + (pos & 1)] = v;
}
// h-region: pos {kk, 50+kk, 100+kk} <- {z1, z2, z1}
__device__ __forceinline__ void stage_zh(__nv_bfloat16* zh, int n, int kk, float v) {
    __nv_bfloat16 z1 = __float2bfloat16(v);
    __nv_bfloat16 z2 = __float2bfloat16(v - __bfloat162float(z1));
    zput(zh, n, kk, z1);
    zput(zh, n, 50 + kk, z2);
    zput(zh, n, 100 + kk, z1);
}
// x-region: pos {d, 60+d, 120+d} <- {z1, z2, z1}
__device__ __forceinline__ void stage_zx(__nv_bfloat16* zx, int n, int d, float v) {
    __nv_bfloat16 z1 = __float2bfloat16(v);
    __nv_bfloat16 z2 = __float2bfloat16(v - __bfloat162float(z1));
    zput(zx, n, d, z1);
    zput(zx, n, 60 + d, z2);
    zput(zx, n, 120 + d, z1);
}

// folded-K weight bits for global column col (0..351), gate row j
__device__ __forceinline__ unsigned short wbits(const float* wh, const float* wx,
                                                int j, int col, int K1x) {
    float w;
    int seg;
    if (col < 160) {
        if (col >= 150) return 0;
        seg = col / 50;
        w = wh[j * HH + (col % 50)];
    } else {
        int xc = col - 160;
        if (xc >= 180) return 0;
        seg = xc / 60;
        int kz = xc % 60;
        if (kz >= K1x) return 0;
        w = wx[j * K1x + kz];
    }
    __nv_bfloat16 w1 = __float2bfloat16(w);
    __nv_bfloat16 res = (seg == 2) ? __float2bfloat16(w - __bfloat162float(w1)) : w1;
    return *reinterpret_cast<unsigned short*>(&res);
}

__global__ void xpose_kernel(const float* __restrict__ x) {
    if (blockIdx.x == 0 && threadIdx.x < NSL * NL) {
        d_prog[threadIdx.x] = 0;
        d_cons[threadIdx.x] = 0;
    }
    int idx = blockIdx.x * blockDim.x + threadIdx.x;  // (b*DIN+d)*T + t
    if (idx >= BATCH * DIN * TT) return;
    int t = idx % TT;
    int bd = idx / TT;
    int d = bd % DIN, b = bd / DIN;
    d_xT[(((size_t)t * NSL + b / BS) * DIN + d) * BS + (b % BS)] = x[idx];
}

__global__ void __launch_bounds__(TPB, 1) lstm_kernel(
    const float* __restrict__ hn,  const float* __restrict__ cn,
    const float* __restrict__ Wih0, const float* __restrict__ Wih,
    const float* __restrict__ Whh, const float* __restrict__ bih,
    const float* __restrict__ bhh, const float* __restrict__ fcw,
    const float* __restrict__ fcb, float* __restrict__ out, int has_state)
{
    extern __shared__ float sm[];
    const int tid  = threadIdx.x;
    const int lane = tid & 31;
    const int w    = tid >> 5;

    // ================= FC consumer role (blocks 128,129) =================
    if (blockIdx.x >= NL * NSL) {
        const int s = blockIdx.x - NL * NSL;
        float* sm_w  = sm + FOFF_W;
        float* sm_fb = sm + FOFF_B;
        float* sm_h  = sm + FOFF_H;
        for (int i = tid; i < DOUT * HH; i += TPB) sm_w[i] = fcw[i];
        for (int i = tid; i < DOUT; i += TPB)      sm_fb[i] = fcb[i];
        __syncthreads();
        const int* prog63 = &d_prog[s * NL + NL - 1];
        for (int t = 0; t < TT; ++t) {
            if (lane == 0) { while (ld_acquire_gpu(prog63) < t + 1) __nanosleep(128); }
            __syncwarp();
            const float* hp = d_hT + ((size_t)t * NSL + s) * HH * BS;
            for (int idx = tid; idx < HH * 4; idx += TPB) {
                float4 v = __ldcg((const float4*)(hp + idx * 4));
                *(float4*)(sm_h + idx * 4) = v;
            }
            __syncthreads();
            if (tid < G4) {
                const int o  = tid % DOUT;
                const int bq = tid / DOUT;
#pragma unroll
                for (int i = 0; i < 4; ++i) {
                    int b = bq * 4 + i;
                    float acc = sm_fb[o];
#pragma unroll 5
                    for (int u = 0; u < HH; ++u)
                        acc = fmaf(sm_h[u * BS + b], sm_w[o * HH + u], acc);
                    out[((size_t)(s * BS + b) * DOUT + o) * TT + t] = sigf(acc);
                }
            }
            __syncthreads();
        }
        return;
    }

    // ========================= LSTM layer role =========================
    const int layer = blockIdx.x >> 1;
    const int s     = blockIdx.x & 1;
    const int b0    = s * BS;
    const int K1x   = (layer == 0) ? DIN : HH;

    float* sm_b = sm + OFF_BIAS;
    float* sm_g = sm + OFF_G;
    __nv_bfloat16* zh = reinterpret_cast<__nv_bfloat16*>(sm + OFF_ZH);

    // ---- init: zero zpacks (NaN safety for pad slots), bias, h0 ----
    for (int i = tid; i < SMEM_FLOATS - OFF_ZH; i += TPB) sm[OFF_ZH + i] = 0.0f;
    for (int jj = tid; jj < G4; jj += TPB)
        sm_b[jj] = bih[layer * G4 + jj] + bhh[layer * G4 + jj];
    __syncthreads();   // zpack zeroed before staging h0
    if (tid < G4) {
        int u = tid % HH, bq = tid / HH;
#pragma unroll
        for (int i = 0; i < 4; ++i) {
            int b = 4 * bq + i;
            stage_zh(zh, b, u, hn[((size_t)layer * BATCH + b0 + b) * HH + u]);
        }
    }
    __syncthreads();

    int* prog_prev = (layer > 0)      ? &d_prog[s * NL + layer - 1] : 0;
    int* cons_next = (layer < NL - 1) ? &d_cons[s * NL + layer + 1] : 0;
    int* prog_me   = &d_prog[s * NL + layer];
    int* cons_me   = &d_cons[s * NL + layer];

    if (w < 13) {
        // ======================= H-group (MMA + C) =======================
        // A fragments into registers (once per layer)
        unsigned int afr[KST][4];
        {
            const float* wh = Whh + (size_t)layer * G4 * HH;
            const float* wx = (layer == 0) ? Wih0 : (Wih + (size_t)(layer - 1) * G4 * HH);
            const int gr = lane >> 2, cp = (lane & 3) * 2;
            for (int kk = 0; kk < KST; ++kk) {
#pragma unroll
                for (int r = 0; r < 4; ++r) {
                    int j = w * 16 + gr + (r & 1) * 8;
                    int c = kk * 16 + cp + (r >> 1) * 8;
                    unsigned int pr = 0;
                    if (j < G4) {
                        pr  = (unsigned int)wbits(wh, wx, j, c, K1x);
                        pr |= ((unsigned int)wbits(wh, wx, j, c + 1, K1x)) << 16;
                    }
                    afr[kk][r] = pr;
                }
            }
        }
        // cell state: threads 0..399, u = tid%50, bq8 = tid/50 (0..7), 2 batches each
        float creg[2];
        const int u_c  = tid % HH;
        const int bq8  = (tid < 400) ? (tid / HH) : 0;
        if (tid < 400) {
#pragma unroll
            for (int i = 0; i < 2; ++i)
                creg[i] = cn[((size_t)layer * BATCH + b0 + 2 * bq8 + i) * HH + u_c];
        }

        const int zb = (lane & 3) * 24 + (lane >> 2);
        const float* zhw = sm + OFF_ZH;
        const int gr = lane >> 2, cp = (lane & 3) * 2;
        const int j0 = w * 16 + gr;

        for (int t = 0; t < TT; ++t) {
            BAR_SYNC(2 + (t & 1), TPB);        // x(t) staged by X-group

            // ---- MMA: gates[208,16] = A . Z ----
            {
                float acc0[4] = {0.f, 0.f, 0.f, 0.f};
                float acc1[4] = {0.f, 0.f, 0.f, 0.f};
                const float* zxw = sm + OFF_ZX + (t & 1) * 2304;
#pragma unroll
                for (int kk = 0; kk < KST; ++kk) {
                    const float* zp = (kk < KH) ? (zhw + kk * 192 + zb)
                                                : (zxw + (kk - KH) * 192 + zb);
                    unsigned int b00 = __float_as_uint(zp[0]);
                    unsigned int b01 = __float_as_uint(zp[96]);
                    unsigned int b10 = __float_as_uint(zp[8]);
                    unsigned int b11 = __float_as_uint(zp[104]);
                    mma_bf16(acc0, afr[kk], b00, b01);
                    mma_bf16(acc1, afr[kk], b10, b11);
                }
                *(float2*)(sm_g + j0 * 20 + cp)           = make_float2(acc0[0], acc0[1]);
                *(float2*)(sm_g + (j0 + 8) * 20 + cp)     = make_float2(acc0[2], acc0[3]);
                *(float2*)(sm_g + j0 * 20 + cp + 8)       = make_float2(acc1[0], acc1[1]);
                *(float2*)(sm_g + (j0 + 8) * 20 + cp + 8) = make_float2(acc1[2], acc1[3]);
            }
            BAR_ARRIVE(4 + (t & 1), TPB);      // x buffer (t&1) free for t+2
            BAR_SYNC(6, 416);                  // sm_g visible within H-group

            // ---- ring backpressure (uniform per H warp) ----
            if (layer < NL - 1 && t >= RINGN) {
                if (lane == 0) { while (ld_acquire_gpu(cons_next) < t - RINGN + 1) __nanosleep(32); }
                __syncwarp();
            }

            // ---- C: cell update (400 threads x 2 batches) ----
            if (tid < 400) {
                float2 gi2 = *(const float2*)(sm_g + u_c * 20 + 2 * bq8);
                float2 gf2 = *(const float2*)(sm_g + (u_c + 50) * 20 + 2 * bq8);
                float2 gg2 = *(const float2*)(sm_g + (u_c + 100) * 20 + 2 * bq8);
                float2 go2 = *(const float2*)(sm_g + (u_c + 150) * 20 + 2 * bq8);
                float bi = sm_b[u_c], bf = sm_b[u_c + 50];
                float bg = sm_b[u_c + 100], bo = sm_b[u_c + 150];
                float gi[2] = {gi2.x + bi, gi2.y + bi};
                float gf[2] = {gf2.x + bf, gf2.y + bf};
                float gg[2] = {gg2.x + bg, gg2.y + bg};
                float go[2] = {go2.x + bo, go2.y + bo};
                float h2[2];
#pragma unroll
                for (int i = 0; i < 2; ++i) {
                    float c = sigf(gf[i]) * creg[i] + sigf(gi[i]) * tanhfast(gg[i]);
                    float h = sigf(go[i]) * tanhfast(c);
                    creg[i] = c;
                    h2[i] = h;
                    stage_zh(zh, 2 * bq8 + i, u_c, h);
                }
                float* dst = (layer < NL - 1)
                    ? (d_ring + (((size_t)layer * RINGN + (t & (RINGN - 1))) * NSL + s) * HH * BS
                       + u_c * BS + 2 * bq8)
                    : (d_hT + ((size_t)t * NSL + s) * HH * BS + u_c * BS + 2 * bq8);
                __stcg((float2*)dst, make_float2(h2[0], h2[1]));
                if (t == TT - 1 && has_state) {
                    size_t base2 = (size_t)BATCH * DOUT * TT;
#pragma unroll
                    for (int i = 0; i < 2; ++i) {
                        size_t sidx = ((size_t)layer * BATCH + b0 + 2 * bq8 + i) * HH + u_c;
                        out[base2 + sidx] = h2[i];
                        out[base2 + (size_t)NL * BATCH * HH + sidx] = creg[i];
                    }
                }
            }
            BAR_SYNC(6, 416);                  // h(t) staged + ring stores drained
            if (tid == 0) st_release_gpu(prog_me, t + 1);
        }
    } else {
        // ======================= X-group (staging) =======================
        for (int t = 0; t < TT; ++t) {
            if (t >= 2) BAR_SYNC(4 + (t & 1), TPB);   // x buffer (t&1) free
            if (layer > 0) {
                if (lane == 0) { while (ld_acquire_gpu(prog_prev) < t + 1) __nanosleep(32); }
                __syncwarp();
            }
            __nv_bfloat16* zx = reinterpret_cast<__nv_bfloat16*>(sm + OFF_ZX + (t & 1) * 2304);
            if (layer == 0) {
                const float* xp = d_xT + ((size_t)t * NSL + s) * DIN * BS;
                for (int idx = tid - 416; idx < DIN * BS; idx += 64) {
                    int d = idx >> 4, n = idx & 15;
                    stage_zx(zx, n, d, xp[d * BS + n]);
                }
            } else {
                const float* rp = d_ring +
                    (((size_t)(layer - 1) * RINGN + (t & (RINGN - 1))) * NSL + s) * HH * BS;
                for (int idx = tid - 416; idx < HH * BS; idx += 64) {
                    int d = idx >> 4, n = idx & 15;
                    stage_zx(zx, n, d, __ldcg(rp + d * BS + n));
                }
            }
            BAR_SYNC(7, 64);                   // staging complete across X warps
            if (tid == 416 && layer > 0 && (((t & 3) == 3) || t == TT - 1))
                st_release_gpu(cons_me, t + 1);
            BAR_ARRIVE(2 + (t & 1), TPB);      // x(t) ready
        }
    }
}

extern "C" void kernel_launch(void* const* d_in, const int* in_sizes, int n_in,
                              void* d_out, int out_size) {
    const float* x    = (const float*)d_in[0];
    const float* hn   = (const float*)d_in[1];
    const float* cn   = (const float*)d_in[2];
    const float* Wih0 = (const float*)d_in[3];
    const float* Wih  = (const float*)d_in[4];
    const float* Whh  = (const float*)d_in[5];
    const float* bih  = (const float*)d_in[6];
    const float* bhh  = (const float*)d_in[7];
    const float* fcw  = (const float*)d_in[8];
    const float* fcb  = (const float*)d_in[9];
    float* out = (float*)d_out;

    const long long full = (long long)BATCH * DOUT * TT + 2LL * NL * BATCH * HH;
    int has_state = (out_size >= full) ? 1 : 0;

    cudaFuncSetAttribute(lstm_kernel, cudaFuncAttributeMaxDynamicSharedMemorySize,
                         SMEM_FLOATS * sizeof(float));

    xpose_kernel<<<(BATCH * DIN * TT + 255) / 256, 256>>>(x);
    lstm_kernel<<<NL * NSL + NSL, TPB, SMEM_FLOATS * sizeof(float)>>>(
        hn, cn, Wih0, Wih, Whh, bih, bhh, fcw, fcb, out, has_state);
}